// round 14
// baseline (speedup 1.0000x reference)
#include <cuda_runtime.h>
#include <cstdint>

#define N_NODES 200000

// ---------- device scratch (no allocs allowed) ----------
__device__ float4 g_z0[N_NODES];   // [x, 1] (UNcentered; centering folded downstream)
__device__ float4 g_a1[N_NODES];   // A z0u   (xyz = A x, w = deg)
__device__ float4 g_a2[N_NODES];   // A a1c   (xyz = g2, w = d2)
__device__ float4 g_a3[N_NODES];   // A a2
__device__ float  g_sum[3];        // column sums of x
__device__ float  g_mat[36];       // Q1,Q2,Q3,u,v,b3

__device__ __forceinline__ void red_add_v4(float4* p, float4 v) {
    asm volatile("red.global.add.v4.f32 [%0], {%1, %2, %3, %4};"
                 :: "l"(p), "f"(v.x), "f"(v.y), "f"(v.z), "f"(v.w)
                 : "memory");
}

// Collapsed 3x3 matrices (round-0 derivation). Also zeroes g_sum (runs first).
__global__ void k_mat(const float* __restrict__ w1, const float* __restrict__ b1,
                      const float* __restrict__ w2, const float* __restrict__ b2,
                      const float* __restrict__ w3, const float* __restrict__ b3) {
    __shared__ float T[3][50];   // T = W3a * W2a
    int tid = threadIdx.x;
    if (tid < 3) g_sum[tid] = 0.f;
    if (tid < 150) {
        int i = tid / 50, k = tid % 50;
        float s = 0.f;
        for (int j = 0; j < 50; j++) s += w3[i*103 + j] * w2[j*53 + k];
        T[i][k] = s;
    }
    __syncthreads();
    if (tid < 9) {                       // Q3 = T * W1
        int i = tid / 3, c = tid % 3;
        float s = 0.f;
        for (int k = 0; k < 50; k++) s += T[i][k] * w1[k*3 + c];
        g_mat[18 + tid] = s;
    } else if (tid < 18) {               // Q2 = W3a*W2b + W3b*W1
        int q = tid - 9; int i = q / 3, c = q % 3;
        float s = 0.f;
        for (int j = 0; j < 50; j++) s += w3[i*103 + j] * w2[j*53 + 50 + c];
        for (int k = 0; k < 50; k++) s += w3[i*103 + 50 + k] * w1[k*3 + c];
        g_mat[9 + q] = s;
    } else if (tid < 27) {               // Q1 = W3c
        int q = tid - 18; int i = q / 3, c = q % 3;
        g_mat[q] = w3[i*103 + 100 + c];
    } else if (tid < 30) {               // u = T * b1
        int i = tid - 27;
        float s = 0.f;
        for (int k = 0; k < 50; k++) s += T[i][k] * b1[k];
        g_mat[27 + i] = s;
    } else if (tid < 33) {               // v = W3a*b2 + W3b*b1
        int i = tid - 30;
        float s = 0.f;
        for (int j = 0; j < 50; j++) s += w3[i*103 + j] * b2[j];
        for (int k = 0; k < 50; k++) s += w3[i*103 + 50 + k] * b1[k];
        g_mat[30 + i] = s;
    } else if (tid < 36) {
        g_mat[tid] = b3[tid - 33];
    }
}

// One node-grid kernel: build z0u=(x,1), zero accumulators, column-sum partials.
__global__ void k_prep(const float* __restrict__ x) {
    int n = blockIdx.x * blockDim.x + threadIdx.x;
    float a = 0.f, b = 0.f, c = 0.f;
    float4 z = make_float4(0.f, 0.f, 0.f, 0.f);
    if (n < N_NODES) {
        a = x[3*n]; b = x[3*n+1]; c = x[3*n+2];
        g_z0[n] = make_float4(a, b, c, 1.0f);
        g_a1[n] = z; g_a2[n] = z; g_a3[n] = z;
    }
    #pragma unroll
    for (int o = 16; o > 0; o >>= 1) {
        a += __shfl_down_sync(0xffffffffu, a, o);
        b += __shfl_down_sync(0xffffffffu, b, o);
        c += __shfl_down_sync(0xffffffffu, c, o);
    }
    __shared__ float sa[8], sb[8], sc[8];
    int w = threadIdx.x >> 5, l = threadIdx.x & 31;
    if (l == 0) { sa[w] = a; sb[w] = b; sc[w] = c; }
    __syncthreads();
    if (threadIdx.x == 0) {
        float ta = 0.f, tb = 0.f, tc = 0.f;
        #pragma unroll
        for (int i = 0; i < 8; i++) { ta += sa[i]; tb += sb[i]; tc += sc[i]; }
        atomicAdd(&g_sum[0], ta);
        atomicAdd(&g_sum[1], tb);
        atomicAdd(&g_sum[2], tc);
    }
}

// One scatter-red pass over all edges, 4 edges/thread (measured-optimal shape).
// On-the-fly centering: v.xyz -= v.w * (sums[c] * fscale). fscale=0 disables.
__global__ void __launch_bounds__(256)
k_scatter(const int* __restrict__ ei, int E,
          const float4* __restrict__ in, float4* __restrict__ out,
          const float* __restrict__ sums, float fscale) {
    float cx = __ldg(sums + 0) * fscale;
    float cy = __ldg(sums + 1) * fscale;
    float cz = __ldg(sums + 2) * fscale;
    int t = blockIdx.x * blockDim.x + threadIdx.x;
    int n4 = E >> 2;
    if (t < n4) {
        int4 s = __ldg((const int4*)ei + t);
        int4 d = __ldg((const int4*)(ei + E) + t);
        float4 v0 = __ldg(in + s.x);
        float4 v1 = __ldg(in + s.y);
        float4 v2 = __ldg(in + s.z);
        float4 v3 = __ldg(in + s.w);
        v0.x -= v0.w * cx; v0.y -= v0.w * cy; v0.z -= v0.w * cz;
        v1.x -= v1.w * cx; v1.y -= v1.w * cy; v1.z -= v1.w * cz;
        v2.x -= v2.w * cx; v2.y -= v2.w * cy; v2.z -= v2.w * cz;
        v3.x -= v3.w * cx; v3.y -= v3.w * cy; v3.z -= v3.w * cz;
        red_add_v4(out + d.x, v0);
        red_add_v4(out + d.y, v1);
        red_add_v4(out + d.z, v2);
        red_add_v4(out + d.w, v3);
    } else {
        int rem = E & 3;
        int q = t - n4;
        if (q < rem) {
            int e = 4 * n4 + q;
            int s = __ldg(ei + e);
            int d = __ldg(ei + E + e);
            float4 v = __ldg(in + s);
            v.x -= v.w * cx; v.y -= v.w * cy; v.z -= v.w * cz;
            red_add_v4(out + d, v);
        }
    }
}

__global__ void k_final(const float* __restrict__ x, float* __restrict__ out) {
    int n = blockIdx.x * blockDim.x + threadIdx.x;
    if (n >= N_NODES) return;
    int r = n % 40;
    if (n < 1960 && (r < 14 || (r >= 25 && r < 39))) {
        out[3*n]   = x[3*n];
        out[3*n+1] = x[3*n+1];
        out[3*n+2] = x[3*n+2];
        return;
    }
    const float inv = 1.0f / (float)N_NODES;
    float m0 = g_sum[0] * inv, m1 = g_sum[1] * inv, m2 = g_sum[2] * inv;
    float4 a1 = g_a1[n], a2 = g_a2[n], a3 = g_a3[n];
    // a1 is RAW (A x, deg): center it here: g1 = a1.xyz - deg*mean
    float g1x = a1.x - a1.w * m0;
    float g1y = a1.y - a1.w * m1;
    float g1z = a1.z - a1.w * m2;
    float mean[3] = {m0, m1, m2};
    #pragma unroll
    for (int c = 0; c < 3; c++) {
        float s = g_mat[33 + c] + mean[c];                 // b3 + mean
        s += g1x  * g_mat[c*3 + 0] + g1y  * g_mat[c*3 + 1] + g1z  * g_mat[c*3 + 2];
        s += a2.x * g_mat[9 + c*3 + 0] + a2.y * g_mat[9 + c*3 + 1] + a2.z * g_mat[9 + c*3 + 2];
        s += a3.x * g_mat[18 + c*3 + 0] + a3.y * g_mat[18 + c*3 + 1] + a3.z * g_mat[18 + c*3 + 2];
        s += a2.w * g_mat[27 + c];   // d2 * u
        s += a1.w * g_mat[30 + c];   // deg * v
        out[3*n + c] = s;
    }
}

// ---------- launch ----------
extern "C" void kernel_launch(void* const* d_in, const int* in_sizes, int n_in,
                              void* d_out, int out_size) {
    const float* x   = (const float*)d_in[0];
    const int*   ei  = (const int*)d_in[1];
    const float* w1  = (const float*)d_in[5];   // c1_w2
    const float* b1  = (const float*)d_in[6];   // c1_b2
    const float* w2  = (const float*)d_in[9];   // c2_w2
    const float* b2  = (const float*)d_in[10];  // c2_b2
    const float* w3  = (const float*)d_in[13];  // c3_w2
    const float* b3  = (const float*)d_in[14];  // c3_b2
    float* out = (float*)d_out;

    int E = in_sizes[1] / 2;

    // Max-L1 carveout for the gather-heavy pass (uses zero smem). Host-side
    // attribute set, idempotent, not a stream op — graph-capture safe.
    static int carveout_done = 0;
    if (!carveout_done) {
        cudaFuncSetAttribute(k_scatter,
                             cudaFuncAttributePreferredSharedMemoryCarveout, 0);
        carveout_done = 1;
    }

    float4 *z0p, *a1p, *a2p, *a3p;
    float  *sump;
    cudaGetSymbolAddress((void**)&z0p, g_z0);
    cudaGetSymbolAddress((void**)&a1p, g_a1);
    cudaGetSymbolAddress((void**)&a2p, g_a2);
    cudaGetSymbolAddress((void**)&a3p, g_a3);
    cudaGetSymbolAddress((void**)&sump, g_sum);

    const int BT = 256;
    int node_grid = (N_NODES + BT - 1) / BT;
    int n_items = (E >> 2) + (E & 3);
    int edge_grid = (n_items + BT - 1) / BT;
    const float invN = 1.0f / (float)N_NODES;

    k_mat<<<1, 192>>>(w1, b1, w2, b2, w3, b3);   // also zeroes g_sum
    k_prep<<<node_grid, BT>>>(x);
    // pass1: z0u -> a1 (raw; no centering, fscale=0)
    k_scatter<<<edge_grid, BT>>>(ei, E, z0p, a1p, sump, 0.0f);
    // pass2: center a1 on the fly
    k_scatter<<<edge_grid, BT>>>(ei, E, a1p, a2p, sump, invN);
    // pass3: a2 already exact
    k_scatter<<<edge_grid, BT>>>(ei, E, a2p, a3p, sump, 0.0f);
    k_final<<<node_grid, BT>>>(x, out);
}

// round 15
// speedup vs baseline: 1.0057x; 1.0057x over previous
#include <cuda_runtime.h>
#include <cstdint>

#define N_NODES 200000

// ---------- device scratch (no allocs allowed) ----------
__device__ float4 g_z0[N_NODES];   // [x, 1] (UNcentered; centering folded downstream)
__device__ float4 g_a1[N_NODES];   // A z0u   (xyz = A x, w = deg)
__device__ float4 g_a2[N_NODES];   // A a1c   (xyz = g2, w = d2)
__device__ float4 g_a3[N_NODES];   // A a2
__device__ float  g_sum[3];        // column sums of x
__device__ float  g_mat[36];       // Q1,Q2,Q3,u,v,b3

__device__ __forceinline__ void red_add_v4(float4* p, float4 v) {
    asm volatile("red.global.add.v4.f32 [%0], {%1, %2, %3, %4};"
                 :: "l"(p), "f"(v.x), "f"(v.y), "f"(v.z), "f"(v.w)
                 : "memory");
}

// Collapsed 3x3 matrices (round-0 derivation). Also zeroes g_sum (runs first).
__global__ void k_mat(const float* __restrict__ w1, const float* __restrict__ b1,
                      const float* __restrict__ w2, const float* __restrict__ b2,
                      const float* __restrict__ w3, const float* __restrict__ b3) {
    __shared__ float T[3][50];   // T = W3a * W2a
    int tid = threadIdx.x;
    if (tid < 3) g_sum[tid] = 0.f;
    if (tid < 150) {
        int i = tid / 50, k = tid % 50;
        float s = 0.f;
        for (int j = 0; j < 50; j++) s += w3[i*103 + j] * w2[j*53 + k];
        T[i][k] = s;
    }
    __syncthreads();
    if (tid < 9) {                       // Q3 = T * W1
        int i = tid / 3, c = tid % 3;
        float s = 0.f;
        for (int k = 0; k < 50; k++) s += T[i][k] * w1[k*3 + c];
        g_mat[18 + tid] = s;
    } else if (tid < 18) {               // Q2 = W3a*W2b + W3b*W1
        int q = tid - 9; int i = q / 3, c = q % 3;
        float s = 0.f;
        for (int j = 0; j < 50; j++) s += w3[i*103 + j] * w2[j*53 + 50 + c];
        for (int k = 0; k < 50; k++) s += w3[i*103 + 50 + k] * w1[k*3 + c];
        g_mat[9 + q] = s;
    } else if (tid < 27) {               // Q1 = W3c
        int q = tid - 18; int i = q / 3, c = q % 3;
        g_mat[q] = w3[i*103 + 100 + c];
    } else if (tid < 30) {               // u = T * b1
        int i = tid - 27;
        float s = 0.f;
        for (int k = 0; k < 50; k++) s += T[i][k] * b1[k];
        g_mat[27 + i] = s;
    } else if (tid < 33) {               // v = W3a*b2 + W3b*b1
        int i = tid - 30;
        float s = 0.f;
        for (int j = 0; j < 50; j++) s += w3[i*103 + j] * b2[j];
        for (int k = 0; k < 50; k++) s += w3[i*103 + 50 + k] * b1[k];
        g_mat[30 + i] = s;
    } else if (tid < 36) {
        g_mat[tid] = b3[tid - 33];
    }
}

// One node-grid kernel: build z0u=(x,1), zero accumulators, column-sum partials.
__global__ void k_prep(const float* __restrict__ x) {
    int n = blockIdx.x * blockDim.x + threadIdx.x;
    float a = 0.f, b = 0.f, c = 0.f;
    float4 z = make_float4(0.f, 0.f, 0.f, 0.f);
    if (n < N_NODES) {
        a = x[3*n]; b = x[3*n+1]; c = x[3*n+2];
        g_z0[n] = make_float4(a, b, c, 1.0f);
        g_a1[n] = z; g_a2[n] = z; g_a3[n] = z;
    }
    #pragma unroll
    for (int o = 16; o > 0; o >>= 1) {
        a += __shfl_down_sync(0xffffffffu, a, o);
        b += __shfl_down_sync(0xffffffffu, b, o);
        c += __shfl_down_sync(0xffffffffu, c, o);
    }
    __shared__ float sa[8], sb[8], sc[8];
    int w = threadIdx.x >> 5, l = threadIdx.x & 31;
    if (l == 0) { sa[w] = a; sb[w] = b; sc[w] = c; }
    __syncthreads();
    if (threadIdx.x == 0) {
        float ta = 0.f, tb = 0.f, tc = 0.f;
        #pragma unroll
        for (int i = 0; i < 8; i++) { ta += sa[i]; tb += sb[i]; tc += sc[i]; }
        atomicAdd(&g_sum[0], ta);
        atomicAdd(&g_sum[1], tb);
        atomicAdd(&g_sum[2], tc);
    }
}

// One scatter-red pass over all edges, 4 edges/thread (measured-optimal shape).
// On-the-fly centering: v.xyz -= v.w * (sums[c] * fscale). fscale=0 disables.
__global__ void __launch_bounds__(256)
k_scatter(const int* __restrict__ ei, int E,
          const float4* __restrict__ in, float4* __restrict__ out,
          const float* __restrict__ sums, float fscale) {
    float cx = __ldg(sums + 0) * fscale;
    float cy = __ldg(sums + 1) * fscale;
    float cz = __ldg(sums + 2) * fscale;
    int t = blockIdx.x * blockDim.x + threadIdx.x;
    int n4 = E >> 2;
    if (t < n4) {
        int4 s = __ldg((const int4*)ei + t);
        int4 d = __ldg((const int4*)(ei + E) + t);
        float4 v0 = __ldg(in + s.x);
        float4 v1 = __ldg(in + s.y);
        float4 v2 = __ldg(in + s.z);
        float4 v3 = __ldg(in + s.w);
        v0.x -= v0.w * cx; v0.y -= v0.w * cy; v0.z -= v0.w * cz;
        v1.x -= v1.w * cx; v1.y -= v1.w * cy; v1.z -= v1.w * cz;
        v2.x -= v2.w * cx; v2.y -= v2.w * cy; v2.z -= v2.w * cz;
        v3.x -= v3.w * cx; v3.y -= v3.w * cy; v3.z -= v3.w * cz;
        red_add_v4(out + d.x, v0);
        red_add_v4(out + d.y, v1);
        red_add_v4(out + d.z, v2);
        red_add_v4(out + d.w, v3);
    } else {
        int rem = E & 3;
        int q = t - n4;
        if (q < rem) {
            int e = 4 * n4 + q;
            int s = __ldg(ei + e);
            int d = __ldg(ei + E + e);
            float4 v = __ldg(in + s);
            v.x -= v.w * cx; v.y -= v.w * cy; v.z -= v.w * cz;
            red_add_v4(out + d, v);
        }
    }
}

__global__ void k_final(const float* __restrict__ x, float* __restrict__ out) {
    int n = blockIdx.x * blockDim.x + threadIdx.x;
    if (n >= N_NODES) return;
    int r = n % 40;
    if (n < 1960 && (r < 14 || (r >= 25 && r < 39))) {
        out[3*n]   = x[3*n];
        out[3*n+1] = x[3*n+1];
        out[3*n+2] = x[3*n+2];
        return;
    }
    const float inv = 1.0f / (float)N_NODES;
    float m0 = g_sum[0] * inv, m1 = g_sum[1] * inv, m2 = g_sum[2] * inv;
    float4 a1 = g_a1[n], a2 = g_a2[n], a3 = g_a3[n];
    // a1 is RAW (A x, deg): center it here: g1 = a1.xyz - deg*mean
    float g1x = a1.x - a1.w * m0;
    float g1y = a1.y - a1.w * m1;
    float g1z = a1.z - a1.w * m2;
    float mean[3] = {m0, m1, m2};
    #pragma unroll
    for (int c = 0; c < 3; c++) {
        float s = g_mat[33 + c] + mean[c];                 // b3 + mean
        s += g1x  * g_mat[c*3 + 0] + g1y  * g_mat[c*3 + 1] + g1z  * g_mat[c*3 + 2];
        s += a2.x * g_mat[9 + c*3 + 0] + a2.y * g_mat[9 + c*3 + 1] + a2.z * g_mat[9 + c*3 + 2];
        s += a3.x * g_mat[18 + c*3 + 0] + a3.y * g_mat[18 + c*3 + 1] + a3.z * g_mat[18 + c*3 + 2];
        s += a2.w * g_mat[27 + c];   // d2 * u
        s += a1.w * g_mat[30 + c];   // deg * v
        out[3*n + c] = s;
    }
}

// ---------- launch ----------
extern "C" void kernel_launch(void* const* d_in, const int* in_sizes, int n_in,
                              void* d_out, int out_size) {
    const float* x   = (const float*)d_in[0];
    const int*   ei  = (const int*)d_in[1];
    const float* w1  = (const float*)d_in[5];   // c1_w2
    const float* b1  = (const float*)d_in[6];   // c1_b2
    const float* w2  = (const float*)d_in[9];   // c2_w2
    const float* b2  = (const float*)d_in[10];  // c2_b2
    const float* w3  = (const float*)d_in[13];  // c3_w2
    const float* b3  = (const float*)d_in[14];  // c3_b2
    float* out = (float*)d_out;

    int E = in_sizes[1] / 2;

    // Max-L1 carveout for the gather-heavy pass (uses zero smem). Host-side
    // attribute set, idempotent, not a stream op — graph-capture safe.
    static int carveout_done = 0;
    if (!carveout_done) {
        cudaFuncSetAttribute(k_scatter,
                             cudaFuncAttributePreferredSharedMemoryCarveout, 0);
        carveout_done = 1;
    }

    float4 *z0p, *a1p, *a2p, *a3p;
    float  *sump;
    cudaGetSymbolAddress((void**)&z0p, g_z0);
    cudaGetSymbolAddress((void**)&a1p, g_a1);
    cudaGetSymbolAddress((void**)&a2p, g_a2);
    cudaGetSymbolAddress((void**)&a3p, g_a3);
    cudaGetSymbolAddress((void**)&sump, g_sum);

    const int BT = 256;
    int node_grid = (N_NODES + BT - 1) / BT;
    int n_items = (E >> 2) + (E & 3);
    int edge_grid = (n_items + BT - 1) / BT;
    const float invN = 1.0f / (float)N_NODES;

    k_mat<<<1, 192>>>(w1, b1, w2, b2, w3, b3);   // also zeroes g_sum
    k_prep<<<node_grid, BT>>>(x);
    // pass1: z0u -> a1 (raw; no centering, fscale=0)
    k_scatter<<<edge_grid, BT>>>(ei, E, z0p, a1p, sump, 0.0f);
    // pass2: center a1 on the fly
    k_scatter<<<edge_grid, BT>>>(ei, E, a1p, a2p, sump, invN);
    // pass3: a2 already exact
    k_scatter<<<edge_grid, BT>>>(ei, E, a2p, a3p, sump, 0.0f);
    k_final<<<node_grid, BT>>>(x, out);
}

// round 16
// speedup vs baseline: 1.0061x; 1.0005x over previous
#include <cuda_runtime.h>
#include <cstdint>

#define N_NODES 200000

// ---------- device scratch (no allocs allowed) ----------
__device__ float4 g_z0[N_NODES];   // [x, 1] (UNcentered; centering folded downstream)
__device__ float4 g_a1[N_NODES];   // A z0u   (xyz = A x, w = deg)
__device__ float4 g_a2[N_NODES];   // A a1c   (xyz = g2, w = d2)
__device__ float4 g_a3[N_NODES];   // A a2
__device__ float  g_sum[3];        // column sums of x
__device__ float  g_mat[36];       // Q1,Q2,Q3,u,v,b3

__device__ __forceinline__ void red_add_v4(float4* p, float4 v) {
    asm volatile("red.global.add.v4.f32 [%0], {%1, %2, %3, %4};"
                 :: "l"(p), "f"(v.x), "f"(v.y), "f"(v.z), "f"(v.w)
                 : "memory");
}

// Collapsed 3x3 matrices (round-0 derivation). Also zeroes g_sum (runs first).
__global__ void k_mat(const float* __restrict__ w1, const float* __restrict__ b1,
                      const float* __restrict__ w2, const float* __restrict__ b2,
                      const float* __restrict__ w3, const float* __restrict__ b3) {
    __shared__ float T[3][50];   // T = W3a * W2a
    int tid = threadIdx.x;
    if (tid < 3) g_sum[tid] = 0.f;
    if (tid < 150) {
        int i = tid / 50, k = tid % 50;
        float s = 0.f;
        for (int j = 0; j < 50; j++) s += w3[i*103 + j] * w2[j*53 + k];
        T[i][k] = s;
    }
    __syncthreads();
    if (tid < 9) {                       // Q3 = T * W1
        int i = tid / 3, c = tid % 3;
        float s = 0.f;
        for (int k = 0; k < 50; k++) s += T[i][k] * w1[k*3 + c];
        g_mat[18 + tid] = s;
    } else if (tid < 18) {               // Q2 = W3a*W2b + W3b*W1
        int q = tid - 9; int i = q / 3, c = q % 3;
        float s = 0.f;
        for (int j = 0; j < 50; j++) s += w3[i*103 + j] * w2[j*53 + 50 + c];
        for (int k = 0; k < 50; k++) s += w3[i*103 + 50 + k] * w1[k*3 + c];
        g_mat[9 + q] = s;
    } else if (tid < 27) {               // Q1 = W3c
        int q = tid - 18; int i = q / 3, c = q % 3;
        g_mat[q] = w3[i*103 + 100 + c];
    } else if (tid < 30) {               // u = T * b1
        int i = tid - 27;
        float s = 0.f;
        for (int k = 0; k < 50; k++) s += T[i][k] * b1[k];
        g_mat[27 + i] = s;
    } else if (tid < 33) {               // v = W3a*b2 + W3b*b1
        int i = tid - 30;
        float s = 0.f;
        for (int j = 0; j < 50; j++) s += w3[i*103 + j] * b2[j];
        for (int k = 0; k < 50; k++) s += w3[i*103 + 50 + k] * b1[k];
        g_mat[30 + i] = s;
    } else if (tid < 36) {
        g_mat[tid] = b3[tid - 33];
    }
}

// One node-grid kernel: build z0u=(x,1), zero accumulators, column-sum partials.
__global__ void k_prep(const float* __restrict__ x) {
    int n = blockIdx.x * blockDim.x + threadIdx.x;
    float a = 0.f, b = 0.f, c = 0.f;
    float4 z = make_float4(0.f, 0.f, 0.f, 0.f);
    if (n < N_NODES) {
        a = x[3*n]; b = x[3*n+1]; c = x[3*n+2];
        g_z0[n] = make_float4(a, b, c, 1.0f);
        g_a1[n] = z; g_a2[n] = z; g_a3[n] = z;
    }
    #pragma unroll
    for (int o = 16; o > 0; o >>= 1) {
        a += __shfl_down_sync(0xffffffffu, a, o);
        b += __shfl_down_sync(0xffffffffu, b, o);
        c += __shfl_down_sync(0xffffffffu, c, o);
    }
    __shared__ float sa[8], sb[8], sc[8];
    int w = threadIdx.x >> 5, l = threadIdx.x & 31;
    if (l == 0) { sa[w] = a; sb[w] = b; sc[w] = c; }
    __syncthreads();
    if (threadIdx.x == 0) {
        float ta = 0.f, tb = 0.f, tc = 0.f;
        #pragma unroll
        for (int i = 0; i < 8; i++) { ta += sa[i]; tb += sb[i]; tc += sc[i]; }
        atomicAdd(&g_sum[0], ta);
        atomicAdd(&g_sum[1], tb);
        atomicAdd(&g_sum[2], tc);
    }
}

// One scatter-red pass over all edges, 4 edges/thread (measured-optimal shape).
// On-the-fly centering: v.xyz -= v.w * (sums[c] * fscale). fscale=0 disables.
__global__ void __launch_bounds__(256)
k_scatter(const int* __restrict__ ei, int E,
          const float4* __restrict__ in, float4* __restrict__ out,
          const float* __restrict__ sums, float fscale) {
    float cx = __ldg(sums + 0) * fscale;
    float cy = __ldg(sums + 1) * fscale;
    float cz = __ldg(sums + 2) * fscale;
    int t = blockIdx.x * blockDim.x + threadIdx.x;
    int n4 = E >> 2;
    if (t < n4) {
        int4 s = __ldg((const int4*)ei + t);
        int4 d = __ldg((const int4*)(ei + E) + t);
        float4 v0 = __ldg(in + s.x);
        float4 v1 = __ldg(in + s.y);
        float4 v2 = __ldg(in + s.z);
        float4 v3 = __ldg(in + s.w);
        v0.x -= v0.w * cx; v0.y -= v0.w * cy; v0.z -= v0.w * cz;
        v1.x -= v1.w * cx; v1.y -= v1.w * cy; v1.z -= v1.w * cz;
        v2.x -= v2.w * cx; v2.y -= v2.w * cy; v2.z -= v2.w * cz;
        v3.x -= v3.w * cx; v3.y -= v3.w * cy; v3.z -= v3.w * cz;
        red_add_v4(out + d.x, v0);
        red_add_v4(out + d.y, v1);
        red_add_v4(out + d.z, v2);
        red_add_v4(out + d.w, v3);
    } else {
        int rem = E & 3;
        int q = t - n4;
        if (q < rem) {
            int e = 4 * n4 + q;
            int s = __ldg(ei + e);
            int d = __ldg(ei + E + e);
            float4 v = __ldg(in + s);
            v.x -= v.w * cx; v.y -= v.w * cy; v.z -= v.w * cz;
            red_add_v4(out + d, v);
        }
    }
}

__global__ void k_final(const float* __restrict__ x, float* __restrict__ out) {
    int n = blockIdx.x * blockDim.x + threadIdx.x;
    if (n >= N_NODES) return;
    int r = n % 40;
    if (n < 1960 && (r < 14 || (r >= 25 && r < 39))) {
        out[3*n]   = x[3*n];
        out[3*n+1] = x[3*n+1];
        out[3*n+2] = x[3*n+2];
        return;
    }
    const float inv = 1.0f / (float)N_NODES;
    float m0 = g_sum[0] * inv, m1 = g_sum[1] * inv, m2 = g_sum[2] * inv;
    float4 a1 = g_a1[n], a2 = g_a2[n], a3 = g_a3[n];
    // a1 is RAW (A x, deg): center it here: g1 = a1.xyz - deg*mean
    float g1x = a1.x - a1.w * m0;
    float g1y = a1.y - a1.w * m1;
    float g1z = a1.z - a1.w * m2;
    float mean[3] = {m0, m1, m2};
    #pragma unroll
    for (int c = 0; c < 3; c++) {
        float s = g_mat[33 + c] + mean[c];                 // b3 + mean
        s += g1x  * g_mat[c*3 + 0] + g1y  * g_mat[c*3 + 1] + g1z  * g_mat[c*3 + 2];
        s += a2.x * g_mat[9 + c*3 + 0] + a2.y * g_mat[9 + c*3 + 1] + a2.z * g_mat[9 + c*3 + 2];
        s += a3.x * g_mat[18 + c*3 + 0] + a3.y * g_mat[18 + c*3 + 1] + a3.z * g_mat[18 + c*3 + 2];
        s += a2.w * g_mat[27 + c];   // d2 * u
        s += a1.w * g_mat[30 + c];   // deg * v
        out[3*n + c] = s;
    }
}

// ---------- launch ----------
extern "C" void kernel_launch(void* const* d_in, const int* in_sizes, int n_in,
                              void* d_out, int out_size) {
    const float* x   = (const float*)d_in[0];
    const int*   ei  = (const int*)d_in[1];
    const float* w1  = (const float*)d_in[5];   // c1_w2
    const float* b1  = (const float*)d_in[6];   // c1_b2
    const float* w2  = (const float*)d_in[9];   // c2_w2
    const float* b2  = (const float*)d_in[10];  // c2_b2
    const float* w3  = (const float*)d_in[13];  // c3_w2
    const float* b3  = (const float*)d_in[14];  // c3_b2
    float* out = (float*)d_out;

    int E = in_sizes[1] / 2;

    // Max-L1 carveout for the gather-heavy pass (uses zero smem). Host-side
    // attribute set, idempotent, not a stream op — graph-capture safe.
    static int carveout_done = 0;
    if (!carveout_done) {
        cudaFuncSetAttribute(k_scatter,
                             cudaFuncAttributePreferredSharedMemoryCarveout, 0);
        carveout_done = 1;
    }

    float4 *z0p, *a1p, *a2p, *a3p;
    float  *sump;
    cudaGetSymbolAddress((void**)&z0p, g_z0);
    cudaGetSymbolAddress((void**)&a1p, g_a1);
    cudaGetSymbolAddress((void**)&a2p, g_a2);
    cudaGetSymbolAddress((void**)&a3p, g_a3);
    cudaGetSymbolAddress((void**)&sump, g_sum);

    const int BT = 256;
    int node_grid = (N_NODES + BT - 1) / BT;
    int n_items = (E >> 2) + (E & 3);
    int edge_grid = (n_items + BT - 1) / BT;
    const float invN = 1.0f / (float)N_NODES;

    k_mat<<<1, 192>>>(w1, b1, w2, b2, w3, b3);   // also zeroes g_sum
    k_prep<<<node_grid, BT>>>(x);
    // pass1: z0u -> a1 (raw; no centering, fscale=0)
    k_scatter<<<edge_grid, BT>>>(ei, E, z0p, a1p, sump, 0.0f);
    // pass2: center a1 on the fly
    k_scatter<<<edge_grid, BT>>>(ei, E, a1p, a2p, sump, invN);
    // pass3: a2 already exact
    k_scatter<<<edge_grid, BT>>>(ei, E, a2p, a3p, sump, 0.0f);
    k_final<<<node_grid, BT>>>(x, out);
}